// round 1
// baseline (speedup 1.0000x reference)
#include <cuda_runtime.h>

#define BB 2
#define C_IN 8
#define U_DIM 7
#define V_DIM 7
#define H_DIM 48
#define W_DIM 48
#define OC 8
#define TH 16        // h-tile rows per block
#define TCOLS 12     // thread columns (each covers 4 pixels in w)
#define PPT 4        // pixels per thread along w
#define NTHREADS 192

// x:    [B][C][U][V][H][W] fp32
// conv: [OC][81*8]  (tap-major, channel minor)  tap = ((i0*3+i1)*3+i2)*3+i3
// bias: [OC]
// out:  [B][OC][U][V][H][W]
__global__ __launch_bounds__(NTHREADS) void conv4d_kernel(
    const float* __restrict__ x,
    const float* __restrict__ conv,
    const float* __restrict__ bias,
    float* __restrict__ out)
{
    // sX: 4 channels x 18 rows x 50 cols (halo of 1 in h and w), stride 50 (even-ish, 2-way max conflict)
    __shared__ float sX[4][18][50];
    // sWt[tap][c][o]: 8 oc weights contiguous -> 2x LDS.128 broadcast
    __shared__ float sWt[81 * 64];

    const int tid = threadIdx.x;
    const int h0  = blockIdx.x * TH;
    const int uv  = blockIdx.y;
    const int u   = uv / V_DIM;
    const int v   = uv % V_DIM;
    const int b   = blockIdx.z;

    // Stage weights (transposed). First __syncthreads below covers this write.
    #pragma unroll 4
    for (int idx = tid; idx < 81 * 64; idx += NTHREADS) {
        const int tap = idx >> 6;
        const int c   = (idx >> 3) & 7;
        const int o   = idx & 7;
        sWt[idx] = conv[o * 648 + tap * 8 + c];
    }

    const int row   = tid / TCOLS;   // 0..15
    const int tcol  = tid % TCOLS;   // 0..11
    const int wbase = tcol * PPT;    // 0,4,...,44

    float acc[8][4];
    #pragma unroll
    for (int o = 0; o < 8; o++)
        #pragma unroll
        for (int p = 0; p < 4; p++)
            acc[o][p] = 0.0f;

    for (int i0 = 0; i0 < 3; i0++) {
        const int uu = u + i0 - 1;
        if (uu < 0 || uu >= U_DIM) continue;
        for (int i1 = 0; i1 < 3; i1++) {
            const int vv = v + i1 - 1;
            if (vv < 0 || vv >= V_DIM) continue;

            const int tapbase = (i0 * 3 + i1) * 9;

            // two channel-groups of 4 to keep SMEM under the 48KB static limit
            for (int cg = 0; cg < 2; cg++) {
                __syncthreads();
                // cooperative load: 4 channel planes, 18x50 each, zero-padded at h/w edges
                for (int idx = tid; idx < 4 * 18 * 50; idx += NTHREADS) {
                    const int cl  = idx / 900;
                    const int rem = idx - cl * 900;
                    const int r   = rem / 50;
                    const int col = rem - r * 50;
                    const int gh  = h0 + r - 1;
                    const int gw  = col - 1;
                    float val = 0.0f;
                    if (gh >= 0 && gh < H_DIM && gw >= 0 && gw < W_DIM) {
                        const int c = cg * 4 + cl;
                        val = x[((((b * C_IN + c) * U_DIM + uu) * V_DIM + vv) * H_DIM + gh) * W_DIM + gw];
                    }
                    sX[cl][r][col] = val;
                }
                __syncthreads();

                #pragma unroll
                for (int cl = 0; cl < 4; cl++) {
                    const int c = cg * 4 + cl;
                    // register-cache the 3x6 x-window covering my 4 pixels x 3x3 taps
                    float xw[3][6];
                    #pragma unroll
                    for (int i2 = 0; i2 < 3; i2++)
                        #pragma unroll
                        for (int j = 0; j < 6; j++)
                            xw[i2][j] = sX[cl][row + i2][wbase + j];

                    #pragma unroll
                    for (int i2 = 0; i2 < 3; i2++) {
                        #pragma unroll
                        for (int i3 = 0; i3 < 3; i3++) {
                            const int tap = tapbase + i2 * 3 + i3;
                            const float4 w0 = *(const float4*)&sWt[(tap * 8 + c) * 8];
                            const float4 w1 = *(const float4*)&sWt[(tap * 8 + c) * 8 + 4];
                            #pragma unroll
                            for (int p = 0; p < 4; p++) {
                                const float xv = xw[i2][i3 + p];
                                acc[0][p] += w0.x * xv;
                                acc[1][p] += w0.y * xv;
                                acc[2][p] += w0.z * xv;
                                acc[3][p] += w0.w * xv;
                                acc[4][p] += w1.x * xv;
                                acc[5][p] += w1.y * xv;
                                acc[6][p] += w1.z * xv;
                                acc[7][p] += w1.w * xv;
                            }
                        }
                    }
                }
            }
        }
    }

    // epilogue: add bias, vectorized store (4 contiguous w per thread)
    const int h = h0 + row;
    #pragma unroll
    for (int o = 0; o < 8; o++) {
        const float bo = __ldg(&bias[o]);
        float4 r4;
        r4.x = acc[o][0] + bo;
        r4.y = acc[o][1] + bo;
        r4.z = acc[o][2] + bo;
        r4.w = acc[o][3] + bo;
        float* dst = &out[((((b * OC + o) * U_DIM + u) * V_DIM + v) * H_DIM + h) * W_DIM + wbase];
        *(float4*)dst = r4;
    }
}

extern "C" void kernel_launch(void* const* d_in, const int* in_sizes, int n_in,
                              void* d_out, int out_size)
{
    const float* x    = (const float*)d_in[0];
    const float* conv = (const float*)d_in[1];
    const float* bias = (const float*)d_in[2];
    float* out        = (float*)d_out;

    dim3 grid(H_DIM / TH, U_DIM * V_DIM, BB);   // (3, 49, 2)
    conv4d_kernel<<<grid, NTHREADS>>>(x, conv, bias, out);
}

// round 2
// speedup vs baseline: 1.3324x; 1.3324x over previous
#include <cuda_runtime.h>

#define U_DIM 7
#define V_DIM 7
#define H_DIM 48
#define W_DIM 48
#define C_IN 8
#define OC 8
#define TH 16        // h rows per block tile
#define TCOLS 24     // thread columns, 2 pixels each
#define NTHREADS 384

// pack (v,v) into a 64-bit f32x2
__device__ __forceinline__ unsigned long long pack2(float v) {
    unsigned long long r;
    asm("mov.b64 %0, {%1, %1};" : "=l"(r) : "f"(v));
    return r;
}
__device__ __forceinline__ void ffma2(unsigned long long& acc,
                                      unsigned long long a,
                                      unsigned long long b) {
    asm("fma.rn.f32x2 %0, %1, %2, %0;" : "+l"(acc) : "l"(a), "l"(b));
}
__device__ __forceinline__ void unpack2(unsigned long long v, float& lo, float& hi) {
    asm("mov.b64 {%0, %1}, %2;" : "=f"(lo), "=f"(hi) : "l"(v));
}

// x:    [2][8][7][7][48][48] fp32
// conv: [8][648]  (oc, tap-major/channel-minor), tap = ((i0*3+i1)*3+i2)*3+i3
// bias: [8]
// out:  [2][8][7][7][48][48]
__global__ __launch_bounds__(NTHREADS, 2) void conv4d_kernel(
    const float* __restrict__ x,
    const float* __restrict__ conv,
    const float* __restrict__ bias,
    float* __restrict__ out)
{
    // 4 channel planes with halo: 18 rows x 50 cols
    __shared__ float sX[4][18][50];
    // weights transposed: [tap][c][o], o contiguous -> LDS.128 = 2 packed oc-pairs
    __shared__ float sWt[81 * 64];

    const int tid = threadIdx.x;
    const int h0  = blockIdx.x * TH;
    const int uv  = blockIdx.y;
    const int u   = uv / V_DIM;
    const int v   = uv % V_DIM;
    const int b   = blockIdx.z;

    // stage weights (transposed); covered by first __syncthreads in the loop
    for (int idx = tid; idx < 81 * 64; idx += NTHREADS) {
        const int tap = idx >> 6;
        const int c   = (idx >> 3) & 7;
        const int o   = idx & 7;
        sWt[idx] = conv[o * 648 + tap * 8 + c];
    }

    const int row   = tid / TCOLS;    // 0..15
    const int tcol  = tid % TCOLS;    // 0..23
    const int wbase = tcol * 2;       // 0,2,...,46 (8B aligned in smem/gmem)

    // acc[p][op]: pixel p (0..1), oc-pair op (0..3): lanes = (oc 2*op, 2*op+1)
    unsigned long long acc[2][4];
    #pragma unroll
    for (int p = 0; p < 2; p++)
        #pragma unroll
        for (int op = 0; op < 4; op++)
            acc[p][op] = 0ULL;

    for (int i0 = 0; i0 < 3; i0++) {
        const int uu = u + i0 - 1;
        if (uu < 0 || uu >= U_DIM) continue;
        for (int i1 = 0; i1 < 3; i1++) {
            const int vv = v + i1 - 1;
            if (vv < 0 || vv >= V_DIM) continue;

            const int tapbase = (i0 * 3 + i1) * 9;

            for (int cg = 0; cg < 2; cg++) {
                __syncthreads();
                // cooperative load: 4 channel planes, 18x50, zero-padded h/w edges
                for (int idx = tid; idx < 4 * 18 * 50; idx += NTHREADS) {
                    const int cl  = idx / 900;
                    const int rem = idx - cl * 900;
                    const int r   = rem / 50;
                    const int col = rem - r * 50;
                    const int gh  = h0 + r - 1;
                    const int gw  = col - 1;
                    float val = 0.0f;
                    if (gh >= 0 && gh < H_DIM && gw >= 0 && gw < W_DIM) {
                        const int c = cg * 4 + cl;
                        val = x[((((b * C_IN + c) * U_DIM + uu) * V_DIM + vv) * H_DIM + gh) * W_DIM + gw];
                    }
                    sX[cl][r][col] = val;
                }
                __syncthreads();

                #pragma unroll
                for (int cl = 0; cl < 4; cl++) {
                    const int c = cg * 4 + cl;
                    #pragma unroll
                    for (int i2 = 0; i2 < 3; i2++) {
                        // 4-wide x window for 2 px + 2 halo (8B-aligned LDS.64 pairs)
                        const float2 xa = *(const float2*)&sX[cl][row + i2][wbase];
                        const float2 xb = *(const float2*)&sX[cl][row + i2][wbase + 2];
                        unsigned long long xq[4];
                        xq[0] = pack2(xa.x);
                        xq[1] = pack2(xa.y);
                        xq[2] = pack2(xb.x);
                        xq[3] = pack2(xb.y);

                        #pragma unroll
                        for (int i3 = 0; i3 < 3; i3++) {
                            const int tap = tapbase + i2 * 3 + i3;
                            const float* wp = &sWt[(tap * 8 + c) * 8];
                            // two LDS.128: 4 packed oc-pairs (broadcast, conflict-free)
                            const ulonglong2 wA = *(const ulonglong2*)wp;        // (o0,o1) (o2,o3)
                            const ulonglong2 wB = *(const ulonglong2*)(wp + 4);  // (o4,o5) (o6,o7)
                            #pragma unroll
                            for (int p = 0; p < 2; p++) {
                                const unsigned long long xv = xq[i3 + p];
                                ffma2(acc[p][0], xv, wA.x);
                                ffma2(acc[p][1], xv, wA.y);
                                ffma2(acc[p][2], xv, wB.x);
                                ffma2(acc[p][3], xv, wB.y);
                            }
                        }
                    }
                }
            }
        }
    }

    // epilogue: unpack oc pairs, add bias, float2 store per oc
    const int h = h0 + row;
    #pragma unroll
    for (int op = 0; op < 4; op++) {
        float v00, v01, v10, v11;   // vPp_oc : pixel, oc-in-pair
        unpack2(acc[0][op], v00, v01);
        unpack2(acc[1][op], v10, v11);
        const int o0 = 2 * op;
        const float b0 = __ldg(&bias[o0]);
        const float b1 = __ldg(&bias[o0 + 1]);
        float2 r0; r0.x = v00 + b0; r0.y = v10 + b0;
        float2 r1; r1.x = v01 + b1; r1.y = v11 + b1;
        float* dst0 = &out[((((b * OC + o0) * U_DIM + u) * V_DIM + v) * H_DIM + h) * W_DIM + wbase];
        float* dst1 = &out[((((b * OC + o0 + 1) * U_DIM + u) * V_DIM + v) * H_DIM + h) * W_DIM + wbase];
        *(float2*)dst0 = r0;
        *(float2*)dst1 = r1;
    }
}

extern "C" void kernel_launch(void* const* d_in, const int* in_sizes, int n_in,
                              void* d_out, int out_size)
{
    const float* x    = (const float*)d_in[0];
    const float* conv = (const float*)d_in[1];
    const float* bias = (const float*)d_in[2];
    float* out        = (float*)d_out;

    dim3 grid(H_DIM / TH, U_DIM * V_DIM, 2);   // (3, 49, 2) = 294 blocks
    conv4d_kernel<<<grid, NTHREADS>>>(x, conv, bias, out);
}

// round 3
// speedup vs baseline: 1.6287x; 1.2224x over previous
#include <cuda_runtime.h>

#define U_DIM 7
#define V_DIM 7
#define H_DIM 48
#define W_DIM 48
#define C_IN 8
#define OC 8
#define TH 8         // h rows per block tile
#define TCOLS 24     // thread columns, 2 pixels each
#define NTHREADS 192
#define XSTRIDE 56   // smem row stride (floats): 224B, 16B-aligned rows
#define XOFF 4       // data at col w+XOFF; halo zeros at col 3 (w=-1) and 52 (w=48)

__device__ __forceinline__ unsigned long long pack2(float v) {
    unsigned long long r;
    asm("mov.b64 %0, {%1, %1};" : "=l"(r) : "f"(v));
    return r;
}
__device__ __forceinline__ void ffma2(unsigned long long& acc,
                                      unsigned long long a,
                                      unsigned long long b) {
    asm("fma.rn.f32x2 %0, %1, %2, %0;" : "+l"(acc) : "l"(a), "l"(b));
}
__device__ __forceinline__ void unpack2(unsigned long long v, float& lo, float& hi) {
    asm("mov.b64 {%0, %1}, %2;" : "=f"(lo), "=f"(hi) : "l"(v));
}

// x:    [2][8][7][7][48][48] fp32
// conv: [8][648]  (oc, tap-major/channel-minor), tap = ((i0*3+i1)*3+i2)*3+i3
// bias: [8]
// out:  [2][8][7][7][48][48]
__global__ __launch_bounds__(NTHREADS, 6) void conv4d_kernel(
    const float* __restrict__ x,
    const float* __restrict__ conv,
    const float* __restrict__ bias,
    float* __restrict__ out)
{
    // 8 channel planes, 10 rows (8 + h-halo), XSTRIDE cols. 17.5 KB
    __shared__ float sX[C_IN][TH + 2][XSTRIDE];
    // weights transposed: [tap][c][o], o contiguous -> LDS.128 = 2 packed oc-pairs. 20.25 KB
    __shared__ float sWt[81 * 64];

    const int tid = threadIdx.x;
    const int h0  = blockIdx.x * TH;
    const int uv  = blockIdx.y;
    const int u   = uv / V_DIM;
    const int v   = uv % V_DIM;
    const int b   = blockIdx.z;

    // one-time: stage weights transposed (27 iters/thread)
    #pragma unroll 4
    for (int idx = tid; idx < 81 * 64; idx += NTHREADS) {
        const int tap = idx >> 6;
        const int c   = (idx >> 3) & 7;
        const int o   = idx & 7;
        sWt[idx] = conv[o * 648 + tap * 8 + c];
    }
    // one-time: zero the w-halo columns (w=-1 and w=48 are ALWAYS out of global range)
    if (tid < 2 * C_IN * (TH + 2)) {
        const int rowi = tid >> 1;
        const int cl   = rowi / (TH + 2);
        const int r    = rowi % (TH + 2);
        sX[cl][r][(tid & 1) ? (XOFF + W_DIM) : (XOFF - 1)] = 0.0f;
    }

    const int row   = tid / TCOLS;    // 0..7
    const int tcol  = tid % TCOLS;    // 0..23
    const int wbase = tcol * 2;       // 0,2,...,46

    // acc[p][op]: pixel p, oc-pair op; lanes = (oc 2*op, 2*op+1)
    unsigned long long acc[2][4];
    #pragma unroll
    for (int p = 0; p < 2; p++)
        #pragma unroll
        for (int op = 0; op < 4; op++)
            acc[p][op] = 0ULL;

    // load-loop decomposition constants: 8ch * 10 rows * 12 float4 = 960 slots, 5/thread
    for (int i0 = 0; i0 < 3; i0++) {
        const int uu = u + i0 - 1;
        if (uu < 0 || uu >= U_DIM) continue;
        for (int i1 = 0; i1 < 3; i1++) {
            const int vv = v + i1 - 1;
            if (vv < 0 || vv >= V_DIM) continue;

            const int tapbase = (i0 * 3 + i1) * 9;
            const float* xsrc = x + ((b * C_IN) * U_DIM * V_DIM + (uu * V_DIM + vv)) * (H_DIM * W_DIM);

            __syncthreads();   // previous compute done before overwriting sX
            #pragma unroll
            for (int k = 0; k < 5; k++) {
                const int idx = tid + k * NTHREADS;
                const int cl  = idx / 120;           // 12 f4 * 10 rows per channel
                const int rem = idx - cl * 120;
                const int r   = rem / 12;
                const int q   = rem - r * 12;
                const int gw  = q * 4;
                const int gh  = h0 + r - 1;
                float4 val = make_float4(0.f, 0.f, 0.f, 0.f);
                if (gh >= 0 && gh < H_DIM) {
                    val = *(const float4*)(xsrc + cl * (U_DIM * V_DIM * H_DIM * W_DIM)
                                                + gh * W_DIM + gw);
                }
                *(float4*)&sX[cl][r][XOFF + gw] = val;   // 16B aligned
            }
            __syncthreads();

            #pragma unroll
            for (int cl = 0; cl < C_IN; cl++) {
                #pragma unroll
                for (int i2 = 0; i2 < 3; i2++) {
                    // window: w' = wbase-1 .. wbase+2  -> smem col 3+wbase .. 6+wbase
                    const float* xr = &sX[cl][row + i2][XOFF - 1 + wbase];
                    unsigned long long xq[4];
                    xq[0] = pack2(xr[0]);
                    xq[1] = pack2(xr[1]);
                    xq[2] = pack2(xr[2]);
                    xq[3] = pack2(xr[3]);

                    #pragma unroll
                    for (int i3 = 0; i3 < 3; i3++) {
                        const int tap = tapbase + i2 * 3 + i3;
                        const float* wp = &sWt[(tap * 8 + cl) * 8];
                        const ulonglong2 wA = *(const ulonglong2*)wp;        // (o0,o1)(o2,o3)
                        const ulonglong2 wB = *(const ulonglong2*)(wp + 4);  // (o4,o5)(o6,o7)
                        #pragma unroll
                        for (int p = 0; p < 2; p++) {
                            const unsigned long long xv = xq[i3 + p];
                            ffma2(acc[p][0], xv, wA.x);
                            ffma2(acc[p][1], xv, wA.y);
                            ffma2(acc[p][2], xv, wB.x);
                            ffma2(acc[p][3], xv, wB.y);
                        }
                    }
                }
            }
        }
    }

    // epilogue
    const int h = h0 + row;
    #pragma unroll
    for (int op = 0; op < 4; op++) {
        float v00, v01, v10, v11;
        unpack2(acc[0][op], v00, v01);
        unpack2(acc[1][op], v10, v11);
        const int o0 = 2 * op;
        const float b0 = __ldg(&bias[o0]);
        const float b1 = __ldg(&bias[o0 + 1]);
        float2 r0; r0.x = v00 + b0; r0.y = v10 + b0;
        float2 r1; r1.x = v01 + b1; r1.y = v11 + b1;
        float* dst0 = &out[((((b * OC + o0) * U_DIM + u) * V_DIM + v) * H_DIM + h) * W_DIM + wbase];
        float* dst1 = &out[((((b * OC + o0 + 1) * U_DIM + u) * V_DIM + v) * H_DIM + h) * W_DIM + wbase];
        *(float2*)dst0 = r0;
        *(float2*)dst1 = r1;
    }
}

extern "C" void kernel_launch(void* const* d_in, const int* in_sizes, int n_in,
                              void* d_out, int out_size)
{
    const float* x    = (const float*)d_in[0];
    const float* conv = (const float*)d_in[1];
    const float* bias = (const float*)d_in[2];
    float* out        = (float*)d_out;

    dim3 grid(H_DIM / TH, U_DIM * V_DIM, 2);   // (6, 49, 2) = 588 blocks
    conv4d_kernel<<<grid, NTHREADS>>>(x, conv, bias, out);
}

// round 4
// speedup vs baseline: 1.6434x; 1.0090x over previous
#include <cuda_runtime.h>
#include <cstdint>

#define U_DIM 7
#define V_DIM 7
#define H_DIM 48
#define W_DIM 48
#define C_IN 8
#define OC 8
#define TH 8         // h rows per block tile
#define TCOLS 24     // thread columns, 2 pixels each
#define NTHREADS 192
#define XSTRIDE 56   // smem row stride (floats): 224B, 16B-aligned rows
#define XOFF 4       // data at col w+XOFF; halo zeros at col 3 (w=-1) and 52 (w=48)
#define CH_STRIDE (U_DIM * V_DIM * H_DIM * W_DIM)   // x per-channel stride

#define SX_FLOATS (2 * C_IN * (TH + 2) * XSTRIDE)   // 8960 floats (two buffers)
#define SMEM_BYTES ((SX_FLOATS + 81 * 64) * 4)      // 56576 B

__device__ __forceinline__ unsigned long long pack2(float v) {
    unsigned long long r;
    asm("mov.b64 %0, {%1, %1};" : "=l"(r) : "f"(v));
    return r;
}
__device__ __forceinline__ void ffma2(unsigned long long& acc,
                                      unsigned long long a,
                                      unsigned long long b) {
    asm("fma.rn.f32x2 %0, %1, %2, %0;" : "+l"(acc) : "l"(a), "l"(b));
}
__device__ __forceinline__ void unpack2(unsigned long long v, float& lo, float& hi) {
    asm("mov.b64 {%0, %1}, %2;" : "=f"(lo), "=f"(hi) : "l"(v));
}

// x:    [2][8][7][7][48][48] fp32
// conv: [8][648]  (oc, tap-major/channel-minor), tap = ((i0*3+i1)*3+i2)*3+i3
// bias: [8]
// out:  [2][8][7][7][48][48]
__global__ __launch_bounds__(NTHREADS, 4) void conv4d_kernel(
    const float* __restrict__ x,
    const float* __restrict__ conv,
    const float* __restrict__ bias,
    float* __restrict__ out)
{
    extern __shared__ float smem[];
    // sX[buf][c][row][col]: 2 x 8ch x 10 rows x 56 cols
    float (*sX)[C_IN][TH + 2][XSTRIDE] =
        (float (*)[C_IN][TH + 2][XSTRIDE])smem;
    // sWt[tap][c][o]: o contiguous -> LDS.128 = 2 packed oc-pairs
    float* sWt = smem + SX_FLOATS;

    const int tid = threadIdx.x;
    const int h0  = blockIdx.x * TH;
    const int uv  = blockIdx.y;
    const int u   = uv / V_DIM;
    const int v   = uv % V_DIM;
    const int b   = blockIdx.z;

    // one-time: stage weights transposed (27 iters/thread)
    #pragma unroll 4
    for (int idx = tid; idx < 81 * 64; idx += NTHREADS) {
        const int tap = idx >> 6;
        const int c   = (idx >> 3) & 7;
        const int o   = idx & 7;
        sWt[idx] = conv[o * 648 + tap * 8 + c];
    }
    // one-time: zero w-halo columns for BOTH buffers (w=-1 / w=48 always OOB)
    for (int idx = tid; idx < 2 * C_IN * (TH + 2); idx += NTHREADS) {
        const int bufi = idx / (C_IN * (TH + 2));
        const int rem  = idx - bufi * (C_IN * (TH + 2));
        const int cl   = rem / (TH + 2);
        const int r    = rem - cl * (TH + 2);
        sX[bufi][cl][r][XOFF - 1]     = 0.0f;
        sX[bufi][cl][r][XOFF + W_DIM] = 0.0f;
    }

    // enumerate valid (i0,i1) phases
    int ph_off[9];   // x offset of (uu,vv) plane within a channel
    int ph_tap[9];
    int nph = 0;
    #pragma unroll
    for (int i0 = 0; i0 < 3; i0++) {
        const int uu = u + i0 - 1;
        if (uu < 0 || uu >= U_DIM) continue;
        #pragma unroll
        for (int i1 = 0; i1 < 3; i1++) {
            const int vv = v + i1 - 1;
            if (vv < 0 || vv >= V_DIM) continue;
            ph_off[nph] = (uu * V_DIM + vv) * (H_DIM * W_DIM);
            ph_tap[nph] = (i0 * 3 + i1) * 9;
            nph++;
        }
    }

    const float* xb = x + (size_t)b * C_IN * CH_STRIDE;

    const int row   = tid / TCOLS;    // 0..7
    const int tcol  = tid % TCOLS;    // 0..23
    const int wbase = tcol * 2;       // 0,2,...,46

    // precompute my 5 cp.async slots (8ch * 10rows * 12 f4 = 960 slots)
    int pf_goff[5];     // gmem offset within (uu,vv) plane set (cl*CH + gh*W + q*4)
    uint32_t pf_sa[5];  // smem byte addr within buffer 0
    int pf_sz[5];
    #pragma unroll
    for (int k = 0; k < 5; k++) {
        const int idx = tid + k * NTHREADS;
        const int cl  = idx / 120;
        const int rem = idx - cl * 120;
        const int r   = rem / 12;
        const int q   = rem - r * 12;
        const int gh  = h0 + r - 1;
        const bool ok = (gh >= 0) && (gh < H_DIM);
        pf_goff[k] = cl * CH_STRIDE + (ok ? gh : 0) * W_DIM + q * 4;
        pf_sa[k]   = (uint32_t)__cvta_generic_to_shared(&sX[0][cl][r][XOFF + q * 4]);
        pf_sz[k]   = ok ? 16 : 0;
    }
    const uint32_t bufstride = C_IN * (TH + 2) * XSTRIDE * 4;   // bytes

    // acc[p][op]: pixel p, oc-pair op; lanes = (oc 2*op, 2*op+1)
    unsigned long long acc[2][4];
    #pragma unroll
    for (int p = 0; p < 2; p++)
        #pragma unroll
        for (int op = 0; op < 4; op++)
            acc[p][op] = 0ULL;

    // prefetch phase 0 into buffer 0
    {
        const float* src = xb + ph_off[0];
        #pragma unroll
        for (int k = 0; k < 5; k++)
            asm volatile("cp.async.ca.shared.global [%0], [%1], 16, %2;"
                         :: "r"(pf_sa[k]), "l"(src + pf_goff[k]), "r"(pf_sz[k]));
        asm volatile("cp.async.commit_group;");
    }

    for (int p = 0; p < nph; p++) {
        asm volatile("cp.async.wait_group 0;");
        __syncthreads();   // data of phase p visible to all; prev compute done

        if (p + 1 < nph) {
            const uint32_t boff = ((p + 1) & 1) * bufstride;
            const float* src = xb + ph_off[p + 1];
            #pragma unroll
            for (int k = 0; k < 5; k++)
                asm volatile("cp.async.ca.shared.global [%0], [%1], 16, %2;"
                             :: "r"(pf_sa[k] + boff), "l"(src + pf_goff[k]), "r"(pf_sz[k]));
            asm volatile("cp.async.commit_group;");
        }

        const int bufi    = p & 1;
        const int tapbase = ph_tap[p];

        #pragma unroll
        for (int cl = 0; cl < C_IN; cl++) {
            #pragma unroll
            for (int i2 = 0; i2 < 3; i2++) {
                const float* xr = &sX[bufi][cl][row + i2][XOFF - 1 + wbase];
                unsigned long long xq[4];
                xq[0] = pack2(xr[0]);
                xq[1] = pack2(xr[1]);
                xq[2] = pack2(xr[2]);
                xq[3] = pack2(xr[3]);

                #pragma unroll
                for (int i3 = 0; i3 < 3; i3++) {
                    const int tap = tapbase + i2 * 3 + i3;
                    const float* wp = &sWt[(tap * 8 + cl) * 8];
                    const ulonglong2 wA = *(const ulonglong2*)wp;        // (o0,o1)(o2,o3)
                    const ulonglong2 wB = *(const ulonglong2*)(wp + 4);  // (o4,o5)(o6,o7)
                    #pragma unroll
                    for (int px = 0; px < 2; px++) {
                        const unsigned long long xv = xq[i3 + px];
                        ffma2(acc[px][0], xv, wA.x);
                        ffma2(acc[px][1], xv, wA.y);
                        ffma2(acc[px][2], xv, wB.x);
                        ffma2(acc[px][3], xv, wB.y);
                    }
                }
            }
        }
    }

    // epilogue
    const int h = h0 + row;
    #pragma unroll
    for (int op = 0; op < 4; op++) {
        float v00, v01, v10, v11;
        unpack2(acc[0][op], v00, v01);
        unpack2(acc[1][op], v10, v11);
        const int o0 = 2 * op;
        const float b0 = __ldg(&bias[o0]);
        const float b1 = __ldg(&bias[o0 + 1]);
        float2 r0; r0.x = v00 + b0; r0.y = v10 + b0;
        float2 r1; r1.x = v01 + b1; r1.y = v11 + b1;
        float* dst0 = &out[((((b * OC + o0) * U_DIM + u) * V_DIM + v) * H_DIM + h) * W_DIM + wbase];
        float* dst1 = &out[((((b * OC + o0 + 1) * U_DIM + u) * V_DIM + v) * H_DIM + h) * W_DIM + wbase];
        *(float2*)dst0 = r0;
        *(float2*)dst1 = r1;
    }
}

extern "C" void kernel_launch(void* const* d_in, const int* in_sizes, int n_in,
                              void* d_out, int out_size)
{
    const float* x    = (const float*)d_in[0];
    const float* conv = (const float*)d_in[1];
    const float* bias = (const float*)d_in[2];
    float* out        = (float*)d_out;

    cudaFuncSetAttribute(conv4d_kernel,
                         cudaFuncAttributeMaxDynamicSharedMemorySize, SMEM_BYTES);

    dim3 grid(H_DIM / TH, U_DIM * V_DIM, 2);   // (6, 49, 2) = 588 blocks
    conv4d_kernel<<<grid, NTHREADS, SMEM_BYTES>>>(x, conv, bias, out);
}